// round 8
// baseline (speedup 1.0000x reference)
#include <cuda_runtime.h>
#include <math_constants.h>
#include <stdint.h>

#define B_ 2
#define T_ 8192
#define HQ_ 32
#define H_ 8
#define D_ 64
#define DR_ 16
#define BS_ 64
#define NB_ 128
#define SEL_ 16
#define GROUPS_ 4
#define TPB 128

// Scratch: Kr[b][h][n][r] = (mean_block K) . Wk.
// exp(logit_scale) is a positive per-head factor (logit_scale is zeros ->
// exp = 1 anyway): monotone, cannot change top-k order -> omitted.
__device__ float g_Kr[B_ * H_ * NB_ * DR_];

// ---------------------------------------------------------------------------
// Kernel 1: block-mean of K, project with Wk.  grid(NB, H, B), 64 threads.
// ---------------------------------------------------------------------------
__global__ void kr_kernel(const float* __restrict__ K,
                          const float* __restrict__ Wk) {
    int n = blockIdx.x, h = blockIdx.y, b = blockIdx.z;
    int d = threadIdx.x;  // 0..63
    const float* kp = K + (((size_t)(b * T_ + n * BS_) * H_ + h) * D_) + d;
    float s = 0.f;
#pragma unroll 8
    for (int tok = 0; tok < BS_; ++tok) s += kp[(size_t)tok * H_ * D_];
    __shared__ float ks[D_];
    ks[d] = s * (1.0f / (float)BS_);
    __syncthreads();
    if (d < DR_) {  // d plays the role of r
        float acc = 0.f;
        const float* w = Wk + h * D_ * DR_ + d;
#pragma unroll
        for (int dd = 0; dd < D_; ++dd) acc += ks[dd] * w[dd * DR_];
        g_Kr[((b * H_ + h) * NB_ + n) * DR_ + d] = acc;
    }
}

// ---------------------------------------------------------------------------
// Kernel 2: per-(b,t,h) routing, literal reference semantics.
// Output written as FLOAT values of the indices (harness __output__ = f32).
// grid(T/TPB, H, B), TPB threads, one thread per (b,t,h).
// ---------------------------------------------------------------------------
__global__ __launch_bounds__(TPB) void route_kernel(const float* __restrict__ Q,
                                                    const float* __restrict__ Wq,
                                                    float* __restrict__ out,
                                                    int nrows) {
    int h = blockIdx.y, b = blockIdx.z;
    int t0 = blockIdx.x * TPB;
    int tid = threadIdx.x;

    __shared__ __align__(16) float wq_s[D_ * DR_];   // 4 KB
    __shared__ __align__(16) float kr_s[NB_ * DR_];  // 8 KB

    for (int i = tid; i < D_ * DR_; i += TPB) wq_s[i] = Wq[h * D_ * DR_ + i];
    for (int i = tid; i < NB_ * DR_; i += TPB)
        kr_s[i] = g_Kr[(b * H_ + h) * NB_ * DR_ + i];
    __syncthreads();

    int t = t0 + tid;
    int tb = t >> 6;  // t_blk
    int row = (b * T_ + t) * H_ + h;
    if (row >= nrows) return;
    float* op = out + (size_t)row * SEL_;

    // ---- Qr[r] = sum_d Q[b,t,h*groups,d] * Wq[h,d,r]  (fp32) ----
    float qr[DR_];
#pragma unroll
    for (int r = 0; r < DR_; ++r) qr[r] = 0.f;
    const float4* qp = (const float4*)(Q +
        ((size_t)(b * T_ + t) * HQ_ + h * GROUPS_) * (size_t)D_);
#pragma unroll
    for (int v = 0; v < D_ / 4; ++v) {
        float4 q4 = qp[v];
        float qs[4] = {q4.x, q4.y, q4.z, q4.w};
#pragma unroll
        for (int j = 0; j < 4; ++j) {
            float qv = qs[j];
            const float4* w4 = (const float4*)(wq_s + (v * 4 + j) * DR_);
            float4 w0 = w4[0], w1 = w4[1], w2 = w4[2], w3 = w4[3];
            qr[0]  += qv * w0.x;  qr[1]  += qv * w0.y;
            qr[2]  += qv * w0.z;  qr[3]  += qv * w0.w;
            qr[4]  += qv * w1.x;  qr[5]  += qv * w1.y;
            qr[6]  += qv * w1.z;  qr[7]  += qv * w1.w;
            qr[8]  += qv * w2.x;  qr[9]  += qv * w2.y;
            qr[10] += qv * w2.z;  qr[11] += qv * w2.w;
            qr[12] += qv * w3.x;  qr[13] += qv * w3.y;
            qr[14] += qv * w3.z;  qr[15] += qv * w3.w;
        }
    }

    // ---- scores for valid blocks n = 0..tb ----
    float sc[NB_];
    for (int n = 0; n <= tb; ++n) {
        const float4* k4 = (const float4*)(kr_s + n * DR_);
        float4 a = k4[0], c = k4[1], e = k4[2], g = k4[3];
        float s = qr[0] * a.x;
        s += qr[1] * a.y;   s += qr[2] * a.z;   s += qr[3] * a.w;
        s += qr[4] * c.x;   s += qr[5] * c.y;   s += qr[6] * c.z;   s += qr[7] * c.w;
        s += qr[8] * e.x;   s += qr[9] * e.y;   s += qr[10] * e.z;  s += qr[11] * e.w;
        s += qr[12] * g.x;  s += qr[13] * g.y;  s += qr[14] * g.z;  s += qr[15] * g.w;
        sc[n] = s;
    }

    // ---- literal stable top-16 (jax.lax.top_k: ties -> lowest index) ----
    // Masked region (n > tb) is -inf; when tb < 15 the k-th pick for k > tb is
    // the lowest untaken index, which is exactly k.
    int picks[SEL_];
#pragma unroll 1
    for (int k = 0; k < SEL_; ++k) {
        if (k <= tb) {
            float best = -CUDART_INF_F;
            int bi = 0;
            for (int n = 0; n <= tb; ++n) {
                if (sc[n] > best) { best = sc[n]; bi = n; }
            }
            picks[k] = bi;
            sc[bi] = -CUDART_INF_F;  // knock out
        } else {
            picks[k] = k;  // -inf tail, ascending index
        }
    }

    // ---- concat locals {tb, max(tb-1,0)}, sort 18, emit first 16 ----
    int arr[SEL_ + 2];
#pragma unroll
    for (int k = 0; k < SEL_; ++k) arr[k] = picks[k];
    arr[SEL_]     = tb;
    arr[SEL_ + 1] = (tb > 0) ? tb - 1 : 0;
#pragma unroll 1
    for (int i = 1; i < SEL_ + 2; ++i) {   // insertion sort, ascending
        int v = arr[i];
        int j = i - 1;
        while (j >= 0 && arr[j] > v) { arr[j + 1] = arr[j]; --j; }
        arr[j + 1] = v;
    }
#pragma unroll
    for (int k = 0; k < SEL_; ++k) op[k] = (float)arr[k];
}

// ---------------------------------------------------------------------------
extern "C" void kernel_launch(void* const* d_in, const int* in_sizes, int n_in,
                              void* d_out, int out_size) {
    // Identify inputs by element count; fall back to insertion order
    // (Q, K, Wq, Wk, logit_scale, block_size, selected_blocks, groups).
    int qi = -1, ki = -1, w1 = -1, w2 = -1;
    for (int i = 0; i < n_in; ++i) {
        int sz = in_sizes[i];
        if (sz == 33554432) qi = i;
        else if (sz == 8388608) ki = i;
        else if (sz == 8192) { if (w1 < 0) w1 = i; else if (w2 < 0) w2 = i; }
    }
    if (qi < 0 || ki < 0 || w1 < 0 || w2 < 0) { qi = 0; ki = 1; w1 = 2; w2 = 3; }

    // If K precedes Q the listing is alphabetical (K,Q,Wk,Wq) -> first
    // 8192-array is Wk; otherwise insertion order (Q,K,Wq,Wk).
    bool alpha = (ki < qi);
    const float* Q  = (const float*)d_in[qi];
    const float* K  = (const float*)d_in[ki];
    const float* Wq = (const float*)d_in[alpha ? w2 : w1];
    const float* Wk = (const float*)d_in[alpha ? w1 : w2];

    int nrows = out_size / SEL_;
    if (nrows <= 0) nrows = B_ * T_ * H_;

    kr_kernel<<<dim3(NB_, H_, B_), 64>>>(K, Wk);
    route_kernel<<<dim3(T_ / TPB, H_, B_), TPB>>>(Q, Wq, (float*)d_out, nrows);
}

// round 9
// speedup vs baseline: 1.8548x; 1.8548x over previous
#include <cuda_runtime.h>
#include <math_constants.h>
#include <stdint.h>

#define B_ 2
#define T_ 8192
#define HQ_ 32
#define H_ 8
#define D_ 64
#define DR_ 16
#define BS_ 64
#define NB_ 128
#define SEL_ 16
#define GROUPS_ 4
#define TPB 128

// Scratch: Kr[b][h][n][r] = (mean_block K) . Wk.
__device__ float g_Kr[B_ * H_ * NB_ * DR_];

// ---------------------------------------------------------------------------
// Kernel 1: block-mean of K, project with Wk.  grid(NB, H, B), 64 threads.
// ---------------------------------------------------------------------------
__global__ void kr_kernel(const float* __restrict__ K,
                          const float* __restrict__ Wk) {
    int n = blockIdx.x, h = blockIdx.y, b = blockIdx.z;
    int d = threadIdx.x;  // 0..63
    const float* kp = K + (((size_t)(b * T_ + n * BS_) * H_ + h) * D_) + d;
    float s = 0.f;
#pragma unroll 8
    for (int tok = 0; tok < BS_; ++tok) s += kp[(size_t)tok * H_ * D_];
    __shared__ float ks[D_];
    ks[d] = s * (1.0f / (float)BS_);
    __syncthreads();
    if (d < DR_) {
        float acc = 0.f;
        const float* w = Wk + h * D_ * DR_ + d;
#pragma unroll
        for (int dd = 0; dd < D_; ++dd) acc += ks[dd] * w[dd * DR_];
        g_Kr[((b * H_ + h) * NB_ + n) * DR_ + d] = acc;
    }
}

// Score for block n — MUST keep this exact accumulation order (matches the
// passing R8 kernel bit-for-bit, keeping rel_err at 6.45e-4).
__device__ __forceinline__ float score_n(const float* __restrict__ kr_s,
                                         const float qr[DR_], int n) {
    const float4* k4 = (const float4*)(kr_s + n * DR_);
    float4 a = k4[0], c = k4[1], e = k4[2], g = k4[3];
    float s = qr[0] * a.x;
    s += qr[1] * a.y;   s += qr[2] * a.z;   s += qr[3] * a.w;
    s += qr[4] * c.x;   s += qr[5] * c.y;   s += qr[6] * c.z;   s += qr[7] * c.w;
    s += qr[8] * e.x;   s += qr[9] * e.y;   s += qr[10] * e.z;  s += qr[11] * e.w;
    s += qr[12] * g.x;  s += qr[13] * g.y;  s += qr[14] * g.z;  s += qr[15] * g.w;
    return s;
}

// ---------------------------------------------------------------------------
// Kernel 2: per-(b,t,h) routing.  grid(T/TPB, H, B), TPB threads.
// ---------------------------------------------------------------------------
__global__ __launch_bounds__(TPB) void route_kernel(const float* __restrict__ Q,
                                                    const float* __restrict__ Wq,
                                                    float* __restrict__ out,
                                                    int nrows) {
    int h = blockIdx.y, b = blockIdx.z;
    int t0 = blockIdx.x * TPB;
    int tid = threadIdx.x;

    __shared__ __align__(16) float wq_s[D_ * DR_];   // 4 KB
    __shared__ __align__(16) float kr_s[NB_ * DR_];  // 8 KB

    for (int i = tid; i < D_ * DR_; i += TPB) wq_s[i] = Wq[h * D_ * DR_ + i];
    for (int i = tid; i < NB_ * DR_; i += TPB)
        kr_s[i] = g_Kr[(b * H_ + h) * NB_ * DR_ + i];
    __syncthreads();

    int t = t0 + tid;
    int tb = t >> 6;  // t_blk (warp-uniform: 32 consecutive t share tb)
    int row = (b * T_ + t) * H_ + h;
    if (row >= nrows) return;
    float* op = out + (size_t)row * SEL_;

    if (tb < SEL_) {
        // top-16 multiset = {0..15}; locals {tb, max(tb-1,0)} join as
        // duplicates. Emit first 16 of the sorted 18-element multiset.
        int l0 = (tb > 0) ? tb - 1 : 0;
        int c = 0;
#pragma unroll 1
        for (int v = 0; v < SEL_ && c < SEL_; ++v) {
            int m = 1 + (v == tb ? 1 : 0) + (v == l0 ? 1 : 0);
            for (int k = 0; k < m && c < SEL_; ++k) op[c++] = (float)v;
        }
        return;
    }

    // ---- Qr[r] = sum_d Q[b,t,h*groups,d] * Wq[h,d,r]  (fp32, same order
    //      as the passing R8 kernel) ----
    float qr[DR_];
#pragma unroll
    for (int r = 0; r < DR_; ++r) qr[r] = 0.f;
    const float4* qp = (const float4*)(Q +
        ((size_t)(b * T_ + t) * HQ_ + h * GROUPS_) * (size_t)D_);
#pragma unroll
    for (int v = 0; v < D_ / 4; ++v) {
        float4 q4 = qp[v];
        float qs[4] = {q4.x, q4.y, q4.z, q4.w};
#pragma unroll
        for (int j = 0; j < 4; ++j) {
            float qv = qs[j];
            const float4* w4 = (const float4*)(wq_s + (v * 4 + j) * DR_);
            float4 w0 = w4[0], w1 = w4[1], w2 = w4[2], w3 = w4[3];
            qr[0]  += qv * w0.x;  qr[1]  += qv * w0.y;
            qr[2]  += qv * w0.z;  qr[3]  += qv * w0.w;
            qr[4]  += qv * w1.x;  qr[5]  += qv * w1.y;
            qr[6]  += qv * w1.z;  qr[7]  += qv * w1.w;
            qr[8]  += qv * w2.x;  qr[9]  += qv * w2.y;
            qr[10] += qv * w2.z;  qr[11] += qv * w2.w;
            qr[12] += qv * w3.x;  qr[13] += qv * w3.y;
            qr[14] += qv * w3.z;  qr[15] += qv * w3.w;
        }
    }

    // ---- Pass 1: fused score + top-16 VALUE chain (registers only) ----
    float vals[SEL_];
#pragma unroll
    for (int j = 0; j < SEL_; ++j) vals[j] = -CUDART_INF_F;
#pragma unroll 1
    for (int n = 0; n <= tb; ++n) {
        float s = score_n(kr_s, qr, n);
        if (s > vals[SEL_ - 1]) {
            float cur = s;
#pragma unroll
            for (int j = 0; j < SEL_; ++j) {
                float mx = fmaxf(vals[j], cur);
                cur = fminf(vals[j], cur);
                vals[j] = mx;
            }
        }
    }

    // ---- threshold + equal-budget (stable top_k: lowest index on ties) ----
    float thr = vals[SEL_ - 1];   // 16th largest; finite since tb >= 16
    int cgt = 0;
#pragma unroll
    for (int j = 0; j < SEL_ - 1; ++j) cgt += (vals[j] > thr) ? 1 : 0;
    int eqb = SEL_ - cgt;         // how many ==thr to take, ascending index

    // ---- Pass 2: recompute scores, gather selected indices ascending ----
    int arr[SEL_ + 2];
#pragma unroll
    for (int k = 0; k < SEL_ + 2; ++k) arr[k] = 0;
    int cnt = 0;
#pragma unroll 1
    for (int n = 0; n <= tb; ++n) {
        float s = score_n(kr_s, qr, n);
        bool gt = (s > thr);
        bool take = gt || ((s == thr) && (eqb > 0));
        if (take) {
            if (!gt) eqb--;
            if (cnt < SEL_) arr[cnt] = n;
            cnt++;
        }
    }

    // ---- append locals {tb-1, tb}, sort 18, emit first 16 ----
    arr[SEL_]     = tb - 1;       // tb >= 16, no clipping needed
    arr[SEL_ + 1] = tb;
#pragma unroll 1
    for (int i = 1; i < SEL_ + 2; ++i) {   // insertion sort, ascending
        int v = arr[i];
        int j = i - 1;
        while (j >= 0 && arr[j] > v) { arr[j + 1] = arr[j]; --j; }
        arr[j + 1] = v;
    }
#pragma unroll
    for (int k = 0; k < SEL_; k += 4) {
        float4 o = make_float4((float)arr[k], (float)arr[k + 1],
                               (float)arr[k + 2], (float)arr[k + 3]);
        *(float4*)(op + k) = o;
    }
}

// ---------------------------------------------------------------------------
extern "C" void kernel_launch(void* const* d_in, const int* in_sizes, int n_in,
                              void* d_out, int out_size) {
    int qi = -1, ki = -1, w1 = -1, w2 = -1;
    for (int i = 0; i < n_in; ++i) {
        int sz = in_sizes[i];
        if (sz == 33554432) qi = i;
        else if (sz == 8388608) ki = i;
        else if (sz == 8192) { if (w1 < 0) w1 = i; else if (w2 < 0) w2 = i; }
    }
    if (qi < 0 || ki < 0 || w1 < 0 || w2 < 0) { qi = 0; ki = 1; w1 = 2; w2 = 3; }

    bool alpha = (ki < qi);  // alphabetical listing => first 8192-array is Wk
    const float* Q  = (const float*)d_in[qi];
    const float* K  = (const float*)d_in[ki];
    const float* Wq = (const float*)d_in[alpha ? w2 : w1];
    const float* Wk = (const float*)d_in[alpha ? w1 : w2];

    int nrows = out_size / SEL_;
    if (nrows <= 0) nrows = B_ * T_ * H_;

    kr_kernel<<<dim3(NB_, H_, B_), 64>>>(K, Wk);
    route_kernel<<<dim3(T_ / TPB, H_, B_), TPB>>>(Q, Wq, (float*)d_out, nrows);
}